// round 16
// baseline (speedup 1.0000x reference)
#include <cuda_runtime.h>
#include <cuda_fp16.h>
#include <cstdint>
#include <cstddef>

// ---------------------------------------------------------------------------
// word (8,2048,1024) f32, sent (8,512,1024) f32, W (1024,1024) f32
// out: combination (8,2048,2048) then g (8,2048,1024)
// mma.sync m16n8k16 fp16, 2-way split, 3-term (R13-proven arithmetic/layout).
// R16: block 128x128 -> 64x128 (4 warps, 128 thr, ~60KB smem) so TWO
// independent CTAs fit per SM: the 2 warps on each SMSP come from different
// blocks -> no shared __syncthreads -> ldmatrix phases of one block overlap
// HMMA phases of the other. Per-warp mainloop is R13 verbatim.
// ---------------------------------------------------------------------------

#define B_      8
#define S_      2048
#define NS_     512
#define E_      1024
#define M_TOT   (B_ * S_)

#define BM 64
#define BN 128
#define BK 32
#define NTHREADS 128

#define HP 40                           // halves per smem row (80 B pitch)
#define TA_H (BM * HP)                  // 2560 halves per A subtile
#define TA  (TA_H * 2)                  // 5120 B
#define TB_H (BN * HP)                  // 5120 halves per B subtile
#define TB  (TB_H * 2)                  // 10240 B
#define A0_OFF 0
#define A1_OFF TA
#define B0_OFF (2 * TA)                 // 10240
#define B1_OFF (B0_OFF + TB)            // 20480
#define STAGE_BYTES (2 * TA + 2 * TB)   // 30720
#define DYN_SMEM (2 * STAGE_BYTES)      // 61440

// ---- persistent scratch ----------------------------------------------------
__device__ float    g_scores[M_TOT * NS_];    // 32 MB fp32 scores
__device__ uint32_t g_Wp[E_ * E_];            //  4 MB packed W
__device__ uint32_t g_sentp[B_ * NS_ * E_];   // 16 MB packed sent (e contig)
__device__ uint32_t g_sentTp[B_ * E_ * NS_];  // 16 MB packed sent^T (n contig)

// ---------------------------------------------------------------------------
__device__ __forceinline__ uint32_t smem_u32(const void* p) {
    uint32_t a;
    asm("{ .reg .u64 t; cvta.to.shared.u64 t, %1; cvt.u32.u64 %0, t; }"
        : "=r"(a) : "l"(p));
    return a;
}

#define LDMX4(r0, r1, r2, r3, addr)                                           \
    asm volatile("ldmatrix.sync.aligned.m8n8.x4.shared.b16 {%0,%1,%2,%3}, [%4];" \
                 : "=r"(r0), "=r"(r1), "=r"(r2), "=r"(r3) : "r"(addr))

__device__ __forceinline__ void mma16816(float* c, const uint32_t* a,
                                         const uint32_t* b) {
    asm volatile(
        "mma.sync.aligned.m16n8k16.row.col.f32.f16.f16.f32 "
        "{%0,%1,%2,%3}, {%4,%5,%6,%7}, {%8,%9}, {%0,%1,%2,%3};"
        : "+f"(c[0]), "+f"(c[1]), "+f"(c[2]), "+f"(c[3])
        : "r"(a[0]), "r"(a[1]), "r"(a[2]), "r"(a[3]), "r"(b[0]), "r"(b[1]));
}

// fp32 pair -> two packed words (h1<<16 | h0), element order preserved.
__device__ __forceinline__ uint2 pack2(float x, float y) {
    __half2 hp = __floats2half2_rn(x, y);
    float2 hf = __half22float2(hp);
    __half2 lp = __floats2half2_rn(x - hf.x, y - hf.y);
    uint32_t hu = *reinterpret_cast<uint32_t*>(&hp);
    uint32_t lu = *reinterpret_cast<uint32_t*>(&lp);
    return make_uint2(__byte_perm(hu, lu, 0x5410), __byte_perm(hu, lu, 0x7632));
}

// ---------------------------------------------------------------------------
// NT GEMM: C[m,n] = sum_k A[m,k]*B[n,k], 3-term fp16 split.
// Block 64x128, 4 warps (warp tile 32x64, wm = wid&1, wn = wid>>1), BK=32,
// register-staged double buffer (R13 control flow). 2 CTAs/SM.
// A fp32 (in-loop split, STS.128); B packed uint32 (PRMT unpack).
// ---------------------------------------------------------------------------
__global__ __launch_bounds__(NTHREADS, 2)
void gemm3hb(const float* __restrict__ A, const uint32_t* __restrict__ Bp,
             float* __restrict__ C, float* __restrict__ C2,
             int lda, int ldb, int ldc, int ldc2, int K,
             size_t aB, size_t bB, size_t cB, size_t c2B)
{
    extern __shared__ char smc[];

    const int tid  = threadIdx.x;
    const int wid  = tid >> 5;
    const int lane = tid & 31;
    const int wm   = wid & 1;       // M offset 32*wm (rows 0..63)
    const int wn   = wid >> 1;      // N offset 64*wn (cols 0..127)
    const int lr   = lane >> 2;
    const int lc   = lane & 3;

    // A loader: 2 threads per row (64 rows), 16 floats each
    const int lrow = tid >> 1;               // 0..63
    const int lkh  = (tid & 1) * 16;         // 0 or 16
    // B loader: 1 thread per row (128 rows), 32 packed words each
    const int brow = tid;                    // 0..127

    const float* Ag = A + (size_t)blockIdx.z * aB
                        + ((size_t)blockIdx.y * BM + lrow) * lda + lkh;
    const uint32_t* Bg = Bp + (size_t)blockIdx.z * bB
                             + ((size_t)blockIdx.x * BN + brow) * ldb;

    const uint32_t offA  = (uint32_t)(lrow * 80 + lkh * 2);   // bytes in A tile
    const uint32_t offB  = (uint32_t)(brow * 80);             // bytes in B tile

    // ldmatrix per-lane addressing (R13-proven pattern)
    const int msel = lane >> 3, mr = lane & 7;
    const int a_r = (msel & 1) * 8 + mr, a_c = (msel >> 1) * 8;
    const int b_r = (msel >> 1) * 8 + mr, b_c = (msel & 1) * 8;

    const uint32_t base_u = smem_u32(smc);
    uint32_t aAdr[2], bAdr[4];
#pragma unroll
    for (int i = 0; i < 2; i++)
        aAdr[i] = base_u + A0_OFF + 2u * ((wm * 32 + i * 16 + a_r) * HP + a_c);
#pragma unroll
    for (int jp = 0; jp < 4; jp++)
        bAdr[jp] = base_u + B0_OFF + 2u * ((wn * 64 + jp * 16 + b_r) * HP + b_c);

    float acc[2][8][4];
#pragma unroll
    for (int i = 0; i < 2; i++)
#pragma unroll
        for (int j = 0; j < 8; j++)
#pragma unroll
            for (int q = 0; q < 4; q++) acc[i][j][q] = 0.f;

    const int NCH = K / BK;

    // A: split 16 fp32 -> h0/h1, 2+2 STS.128
#define STASH_A(stc_, sa)                                                      \
    do {                                                                       \
        uint32_t H0_[8], H1_[8];                                               \
        _Pragma("unroll")                                                      \
        for (int q = 0; q < 4; q++) {                                          \
            float4 a = (sa)[q];                                                \
            __half2 h0a = __floats2half2_rn(a.x, a.y);                         \
            __half2 h0b = __floats2half2_rn(a.z, a.w);                         \
            float2 ba = __half22float2(h0a), bb = __half22float2(h0b);         \
            __half2 h1a = __floats2half2_rn(a.x - ba.x, a.y - ba.y);           \
            __half2 h1b = __floats2half2_rn(a.z - bb.x, a.w - bb.y);           \
            H0_[2*q]   = *reinterpret_cast<uint32_t*>(&h0a);                   \
            H0_[2*q+1] = *reinterpret_cast<uint32_t*>(&h0b);                   \
            H1_[2*q]   = *reinterpret_cast<uint32_t*>(&h1a);                   \
            H1_[2*q+1] = *reinterpret_cast<uint32_t*>(&h1b);                   \
        }                                                                      \
        *(uint4*)((stc_) + A0_OFF + offA)      = make_uint4(H0_[0], H0_[1], H0_[2], H0_[3]); \
        *(uint4*)((stc_) + A0_OFF + offA + 16) = make_uint4(H0_[4], H0_[5], H0_[6], H0_[7]); \
        *(uint4*)((stc_) + A1_OFF + offA)      = make_uint4(H1_[0], H1_[1], H1_[2], H1_[3]); \
        *(uint4*)((stc_) + A1_OFF + offA + 16) = make_uint4(H1_[4], H1_[5], H1_[6], H1_[7]); \
    } while (0)

    // B: 32 packed words (full row) -> 16 h0-pair words + 16 h1-pair words
#define STASH_B(stc_, pb)                                                      \
    do {                                                                       \
        uint32_t g0_[16], g1_[16];                                             \
        _Pragma("unroll")                                                      \
        for (int q = 0; q < 8; q++) {                                          \
            g0_[2*q]   = __byte_perm((pb)[q].x, (pb)[q].y, 0x5410);            \
            g0_[2*q+1] = __byte_perm((pb)[q].z, (pb)[q].w, 0x5410);            \
            g1_[2*q]   = __byte_perm((pb)[q].x, (pb)[q].y, 0x7632);            \
            g1_[2*q+1] = __byte_perm((pb)[q].z, (pb)[q].w, 0x7632);            \
        }                                                                      \
        _Pragma("unroll")                                                      \
        for (int h = 0; h < 4; h++) {                                          \
            *(uint4*)((stc_) + B0_OFF + offB + 16 * h) =                       \
                make_uint4(g0_[4*h], g0_[4*h+1], g0_[4*h+2], g0_[4*h+3]);      \
            *(uint4*)((stc_) + B1_OFF + offB + 16 * h) =                       \
                make_uint4(g1_[4*h], g1_[4*h+1], g1_[4*h+2], g1_[4*h+3]);      \
        }                                                                      \
    } while (0)

    // ---- preload chunk 0 --------------------------------------------------
    {
        float4 sa[4];
        uint4  pb[8];
#pragma unroll
        for (int q = 0; q < 4; q++) sa[q] = *(const float4*)(Ag + 4 * q);
#pragma unroll
        for (int q = 0; q < 8; q++) pb[q] = *(const uint4*)(Bg + 4 * q);
        STASH_A(smc, sa);
        STASH_B(smc, pb);
    }
    __syncthreads();

    // ---- main loop (R13 double-buffer structure) --------------------------
    for (int c = 0; c < NCH; c++) {
        const int s = c & 1;
        const bool hasNext = (c + 1 < NCH);

        float4 sa[4];
        uint4  pb[8];
        if (hasNext) {
            const float*    ap = Ag + (size_t)(c + 1) * BK;
            const uint32_t* bp = Bg + (size_t)(c + 1) * BK;
#pragma unroll
            for (int q = 0; q < 4; q++) sa[q] = *(const float4*)(ap + 4 * q);
#pragma unroll
            for (int q = 0; q < 8; q++) pb[q] = *(const uint4*)(bp + 4 * q);
        }

        const uint32_t so = (uint32_t)s * STAGE_BYTES;
#pragma unroll
        for (int ks = 0; ks < 2; ks++) {
            const uint32_t ko = so + ks * 32u;

            uint32_t a0[2][4], a1[2][4];
#pragma unroll
            for (int i = 0; i < 2; i++) {
                LDMX4(a0[i][0], a0[i][1], a0[i][2], a0[i][3], aAdr[i] + ko);
                LDMX4(a1[i][0], a1[i][1], a1[i][2], a1[i][3],
                      aAdr[i] + ko + TA);
            }
            uint32_t b0[8][2], b1[8][2];
#pragma unroll
            for (int jp = 0; jp < 4; jp++) {
                LDMX4(b0[2 * jp][0], b0[2 * jp][1], b0[2 * jp + 1][0],
                      b0[2 * jp + 1][1], bAdr[jp] + ko);
                LDMX4(b1[2 * jp][0], b1[2 * jp][1], b1[2 * jp + 1][0],
                      b1[2 * jp + 1][1], bAdr[jp] + ko + TB);
            }
#pragma unroll
            for (int i = 0; i < 2; i++)
#pragma unroll
                for (int j = 0; j < 8; j++) {
                    mma16816(acc[i][j], a0[i], b0[j]);
                    mma16816(acc[i][j], a0[i], b1[j]);
                    mma16816(acc[i][j], a1[i], b0[j]);
                }
        }

        if (hasNext) {
            char* st = smc + (s ^ 1) * STAGE_BYTES;
            STASH_A(st, sa);
            STASH_B(st, pb);
        }
        __syncthreads();
    }
#undef STASH_A
#undef STASH_B

    // ---- epilogue ---------------------------------------------------------
    float* Cb  = C + (size_t)blockIdx.z * cB + (size_t)blockIdx.x * BN;
    float* C2b = C2 ? C2 + (size_t)blockIdx.z * c2B + (size_t)blockIdx.x * BN
                    : nullptr;
#pragma unroll
    for (int i = 0; i < 2; i++) {
        const size_t mTop = (size_t)blockIdx.y * BM + wm * 32 + i * 16 + lr;
#pragma unroll
        for (int j = 0; j < 8; j++) {
            const int n0 = wn * 64 + j * 8 + 2 * lc;
            float2 v0 = make_float2(acc[i][j][0], acc[i][j][1]);
            float2 v1 = make_float2(acc[i][j][2], acc[i][j][3]);
            *(float2*)(Cb + mTop * ldc + n0)       = v0;
            *(float2*)(Cb + (mTop + 8) * ldc + n0) = v1;
            if (C2b) {
                *(float2*)(C2b + mTop * ldc2 + n0)       = v0;
                *(float2*)(C2b + (mTop + 8) * ldc2 + n0) = v1;
            }
        }
    }
}

// ---------------------------------------------------------------------------
// Elementwise fp32 -> packed uint32, same indexing.
// ---------------------------------------------------------------------------
__global__ __launch_bounds__(256)
void pack_f32(const float* __restrict__ in, uint2* __restrict__ out, int n2)
{
    int i = blockIdx.x * 256 + threadIdx.x;
    if (i < n2) {
        float2 v = ((const float2*)in)[i];
        out[i] = pack2(v.x, v.y);
    }
}

// ---------------------------------------------------------------------------
// sent (b,512,1024) fp32 -> packed sent^T (b,1024,512)
// ---------------------------------------------------------------------------
__global__ __launch_bounds__(256)
void transpose_pack(const float* __restrict__ sent, uint32_t* __restrict__ outp)
{
    __shared__ float t[32][33];
    const int b  = blockIdx.z;
    const int n0 = blockIdx.y * 32;
    const int e0 = blockIdx.x * 32;
    const int x = threadIdx.x, y = threadIdx.y;

    const float* src = sent + ((size_t)b * NS_ + n0) * E_ + e0;
#pragma unroll
    for (int k = 0; k < 4; k++)
        t[y + 8 * k][x] = src[(size_t)(y + 8 * k) * E_ + x];
    __syncthreads();
    const size_t dbase = ((size_t)b * E_ + e0) * NS_ + n0;
#pragma unroll
    for (int k = 0; k < 4; k++) {
        float v = t[x][y + 8 * k];
        __half h0 = __float2half_rn(v);
        __half h1 = __float2half_rn(v - __half2float(h0));
        outp[dbase + (size_t)(y + 8 * k) * NS_ + x] =
            ((uint32_t)__half_as_ushort(h1) << 16) | __half_as_ushort(h0);
    }
}

// ---------------------------------------------------------------------------
// In-place stable softmax over last dim (512) of g_scores.
// ---------------------------------------------------------------------------
__global__ __launch_bounds__(256)
void softmax_rows()
{
    __shared__ float redMax[8];
    __shared__ float redSum[8];

    float* row = g_scores + (size_t)blockIdx.x * NS_;
    const int t = threadIdx.x;

    float2 v = reinterpret_cast<float2*>(row)[t];

    float m = fmaxf(v.x, v.y);
#pragma unroll
    for (int o = 16; o > 0; o >>= 1)
        m = fmaxf(m, __shfl_xor_sync(0xffffffffu, m, o));
    if ((t & 31) == 0) redMax[t >> 5] = m;
    __syncthreads();
    float mAll = redMax[0];
#pragma unroll
    for (int i = 1; i < 8; i++) mAll = fmaxf(mAll, redMax[i]);

    float e0 = expf(v.x - mAll);
    float e1 = expf(v.y - mAll);
    float s = e0 + e1;
#pragma unroll
    for (int o = 16; o > 0; o >>= 1)
        s += __shfl_xor_sync(0xffffffffu, s, o);
    if ((t & 31) == 0) redSum[t >> 5] = s;
    __syncthreads();
    float sAll = 0.f;
#pragma unroll
    for (int i = 0; i < 8; i++) sAll += redSum[i];

    const float inv = 1.0f / sAll;
    reinterpret_cast<float2*>(row)[t] = make_float2(e0 * inv, e1 * inv);
}

// ---------------------------------------------------------------------------
extern "C" void kernel_launch(void* const* d_in, const int* in_sizes, int n_in,
                              void* d_out, int out_size)
{
    (void)out_size;
    const float* word = nullptr;
    const float* sent = nullptr;
    const float* W    = nullptr;
    for (int i = 0; i < n_in; i++) {
        if      (in_sizes[i] == M_TOT * E_)    word = (const float*)d_in[i];
        else if (in_sizes[i] == B_ * NS_ * E_) sent = (const float*)d_in[i];
        else if (in_sizes[i] == E_ * E_)       W    = (const float*)d_in[i];
    }

    float* out  = (float*)d_out;
    float* comb = out;                               // (8, 2048, 2048)
    float* gout = out + (size_t)M_TOT * 2 * E_;      // (8, 2048, 1024)

    float    *scores;
    uint32_t *Wp, *sentp, *sentTp;
    cudaGetSymbolAddress((void**)&scores, g_scores);
    cudaGetSymbolAddress((void**)&Wp,     g_Wp);
    cudaGetSymbolAddress((void**)&sentp,  g_sentp);
    cudaGetSymbolAddress((void**)&sentTp, g_sentTp);

    cudaFuncSetAttribute(gemm3hb,
                         cudaFuncAttributeMaxDynamicSharedMemorySize, DYN_SMEM);

    // 0) pack B-side operands (bandwidth-bound)
    pack_f32<<<(E_ * E_ / 2 + 255) / 256, 256>>>(W, (uint2*)Wp, E_ * E_ / 2);
    pack_f32<<<(B_ * NS_ * E_ / 2 + 255) / 256, 256>>>(sent, (uint2*)sentp,
                                                       B_ * NS_ * E_ / 2);
    transpose_pack<<<dim3(E_ / 32, NS_ / 32, B_), dim3(32, 8)>>>(sent, sentTp);

    // 1) w = word @ W^T -> combination[:, :1024]   (M=16384, N=1024, K=1024)
    gemm3hb<<<dim3(E_ / BN, M_TOT / BM, 1), NTHREADS, DYN_SMEM>>>(
        word, Wp, comb, nullptr,
        E_, E_, 2 * E_, 0, E_,
        0, 0, 0, 0);

    // 2) scores[b] = w[b] @ sent[b]^T -> g_scores  (M=2048, N=512, K=1024)
    gemm3hb<<<dim3(NS_ / BN, S_ / BM, B_), NTHREADS, DYN_SMEM>>>(
        comb, sentp, scores, nullptr,
        2 * E_, E_, NS_, 0, E_,
        (size_t)S_ * 2 * E_, (size_t)NS_ * E_, (size_t)S_ * NS_, 0);

    // 3) softmax over 512 sentence scores per (b,s) row
    softmax_rows<<<M_TOT, 256>>>();

    // 4) g[b] = att[b] @ sent[b] -> comb[:, 1024:] AND g  (M=2048, N=1024, K=512)
    gemm3hb<<<dim3(E_ / BN, S_ / BM, B_), NTHREADS, DYN_SMEM>>>(
        scores, sentTp, comb + E_, gout,
        NS_, NS_, 2 * E_, E_, NS_,
        (size_t)S_ * NS_, (size_t)E_ * NS_, (size_t)S_ * 2 * E_, (size_t)S_ * E_);
}

// round 17
// speedup vs baseline: 1.3929x; 1.3929x over previous
#include <cuda_runtime.h>
#include <cuda_fp16.h>
#include <cstdint>
#include <cstddef>

// ---------------------------------------------------------------------------
// word (8,2048,1024) f32, sent (8,512,1024) f32, W (1024,1024) f32
// out: combination (8,2048,2048) then g (8,2048,1024)
// Base = R13 passing kernel (128x128x32, A fp32 in-loop split, B packed).
// R17 change: the two cross terms (a0*b1, a1*b0) accumulate into a SHARED
// fp16 accumulator via f16-acc HMMA (2x rate if H2 holds); main term a0*b0
// stays fp32-acc. Epilogue adds the converted cross term.
// ---------------------------------------------------------------------------

#define B_      8
#define S_      2048
#define NS_     512
#define E_      1024
#define M_TOT   (B_ * S_)

#define BM 128
#define BN 128
#define BK 32
#define NTHREADS 256

#define HP 40                          // halves per smem row (80 B pitch)
#define TILE_H (128 * HP)              // 5120 halves per tile
#define TILE_BYTES (TILE_H * 2)        // 10240
#define STAGE_H (4 * TILE_H)           // A0 A1 B0 B1
#define STAGE_BYTES (STAGE_H * 2)      // 40960
#define DYN_SMEM (2 * STAGE_BYTES)     // 81920

// ---- persistent scratch ----------------------------------------------------
__device__ float    g_scores[M_TOT * NS_];    // 32 MB fp32 scores
__device__ uint32_t g_Wp[E_ * E_];            //  4 MB packed W
__device__ uint32_t g_sentp[B_ * NS_ * E_];   // 16 MB packed sent (e contig)
__device__ uint32_t g_sentTp[B_ * E_ * NS_];  // 16 MB packed sent^T (n contig)

// ---------------------------------------------------------------------------
__device__ __forceinline__ uint32_t smem_u32(const void* p) {
    uint32_t a;
    asm("{ .reg .u64 t; cvta.to.shared.u64 t, %1; cvt.u32.u64 %0, t; }"
        : "=r"(a) : "l"(p));
    return a;
}

#define LDMX4(r0, r1, r2, r3, addr)                                           \
    asm volatile("ldmatrix.sync.aligned.m8n8.x4.shared.b16 {%0,%1,%2,%3}, [%4];" \
                 : "=r"(r0), "=r"(r1), "=r"(r2), "=r"(r3) : "r"(addr))

// fp32-accumulator HMMA (main term)
__device__ __forceinline__ void mma_f32(float* c, const uint32_t* a,
                                        const uint32_t* b) {
    asm volatile(
        "mma.sync.aligned.m16n8k16.row.col.f32.f16.f16.f32 "
        "{%0,%1,%2,%3}, {%4,%5,%6,%7}, {%8,%9}, {%0,%1,%2,%3};"
        : "+f"(c[0]), "+f"(c[1]), "+f"(c[2]), "+f"(c[3])
        : "r"(a[0]), "r"(a[1]), "r"(a[2]), "r"(a[3]), "r"(b[0]), "r"(b[1]));
}

// fp16-accumulator HMMA (cross terms; 2x rate if H2 holds)
__device__ __forceinline__ void mma_f16(uint32_t* c, const uint32_t* a,
                                        const uint32_t* b) {
    asm volatile(
        "mma.sync.aligned.m16n8k16.row.col.f16.f16.f16.f16 "
        "{%0,%1}, {%2,%3,%4,%5}, {%6,%7}, {%0,%1};"
        : "+r"(c[0]), "+r"(c[1])
        : "r"(a[0]), "r"(a[1]), "r"(a[2]), "r"(a[3]), "r"(b[0]), "r"(b[1]));
}

// fp32 pair -> two packed words (h1<<16 | h0), element order preserved.
__device__ __forceinline__ uint2 pack2(float x, float y) {
    __half2 hp = __floats2half2_rn(x, y);
    float2 hf = __half22float2(hp);
    __half2 lp = __floats2half2_rn(x - hf.x, y - hf.y);
    uint32_t hu = *reinterpret_cast<uint32_t*>(&hp);
    uint32_t lu = *reinterpret_cast<uint32_t*>(&lp);
    return make_uint2(__byte_perm(hu, lu, 0x5410), __byte_perm(hu, lu, 0x7632));
}

// ---------------------------------------------------------------------------
// NT GEMM: C[m,n] = sum_k A[m,k]*B[n,k], 3-term fp16 split.
// A fp32 (in-loop split); B packed uint32 (PRMT unpack).
// 128x128x32 tiles, R13 register-staged double buffer. Optional dual C2.
// ---------------------------------------------------------------------------
__global__ __launch_bounds__(NTHREADS, 1)
void gemm3hb(const float* __restrict__ A, const uint32_t* __restrict__ Bp,
             float* __restrict__ C, float* __restrict__ C2,
             int lda, int ldb, int ldc, int ldc2, int K,
             size_t aB, size_t bB, size_t cB, size_t c2B)
{
    extern __shared__ __half smh[];
    char* smc = (char*)smh;

    const int tid  = threadIdx.x;
    const int wid  = tid >> 5;
    const int lane = tid & 31;
    const int wm   = wid & 3;
    const int wn   = wid >> 2;
    const int lr   = lane >> 2;
    const int lc   = lane & 3;

    // loader mapping: 2 threads per row, each covers 16 of the 32 k-elems
    const int lrow = tid >> 1;
    const int lkh  = (tid & 1) * 16;

    const float* Ag = A + (size_t)blockIdx.z * aB
                        + ((size_t)blockIdx.y * BM + lrow) * lda + lkh;
    const uint32_t* Bg = Bp + (size_t)blockIdx.z * bB
                             + ((size_t)blockIdx.x * BN + lrow) * ldb + lkh;

    // ldmatrix per-lane addressing (R13-proven)
    const int msel = lane >> 3, mr = lane & 7;
    const int a_r = (msel & 1) * 8 + mr, a_c = (msel >> 1) * 8;
    const int b_r = (msel >> 1) * 8 + mr, b_c = (msel & 1) * 8;

    const uint32_t base_u = smem_u32(smh);
    uint32_t aAdr[2], bAdr[4];
#pragma unroll
    for (int i = 0; i < 2; i++)
        aAdr[i] = base_u + 2u * ((wm * 32 + i * 16 + a_r) * HP + a_c);
#pragma unroll
    for (int jp = 0; jp < 4; jp++)
        bAdr[jp] = base_u + 2u * (2 * TILE_H + (wn * 64 + jp * 16 + b_r) * HP + b_c);

    float acc[2][8][4];
    uint32_t xacc[2][8][2];
#pragma unroll
    for (int i = 0; i < 2; i++)
#pragma unroll
        for (int j = 0; j < 8; j++) {
#pragma unroll
            for (int q = 0; q < 4; q++) acc[i][j][q] = 0.f;
            xacc[i][j][0] = 0u; xacc[i][j][1] = 0u;
        }

    const int NCH = K / BK;
    const int sts_pos = lrow * HP + lkh;           // half index within a tile
    const uint32_t sts_b = (uint32_t)sts_pos * 2;  // byte offset

    // A split+store (R13 verbatim) ------------------------------------------
#define STASH_A(st, sa)                                                        \
    do {                                                                       \
        _Pragma("unroll")                                                      \
        for (int q = 0; q < 4; q++) {                                          \
            float4 a = (sa)[q];                                                \
            __half2 h0a = __floats2half2_rn(a.x, a.y);                         \
            __half2 h0b = __floats2half2_rn(a.z, a.w);                         \
            float2 ba = __half22float2(h0a), bb = __half22float2(h0b);         \
            __half2 h1a = __floats2half2_rn(a.x - ba.x, a.y - ba.y);           \
            __half2 h1b = __floats2half2_rn(a.z - bb.x, a.w - bb.y);           \
            __half2* p0 = (__half2*)((st) + sts_pos + 4 * q);                  \
            __half2* p1 = (__half2*)((st) + TILE_H + sts_pos + 4 * q);         \
            p0[0] = h0a; p0[1] = h0b; p1[0] = h1a; p1[1] = h1b;                \
        }                                                                      \
    } while (0)

    // B unpack+store (R13 verbatim) -----------------------------------------
#define STASH_B(stc_, pb)                                                      \
    do {                                                                       \
        uint32_t g0_[8], g1_[8];                                               \
        _Pragma("unroll")                                                      \
        for (int q = 0; q < 4; q++) {                                          \
            g0_[2*q]   = __byte_perm((pb)[q].x, (pb)[q].y, 0x5410);            \
            g0_[2*q+1] = __byte_perm((pb)[q].z, (pb)[q].w, 0x5410);            \
            g1_[2*q]   = __byte_perm((pb)[q].x, (pb)[q].y, 0x7632);            \
            g1_[2*q+1] = __byte_perm((pb)[q].z, (pb)[q].w, 0x7632);            \
        }                                                                      \
        *(uint4*)((stc_) + 2 * TILE_BYTES + sts_b)      = make_uint4(g0_[0], g0_[1], g0_[2], g0_[3]); \
        *(uint4*)((stc_) + 2 * TILE_BYTES + sts_b + 16) = make_uint4(g0_[4], g0_[5], g0_[6], g0_[7]); \
        *(uint4*)((stc_) + 3 * TILE_BYTES + sts_b)      = make_uint4(g1_[0], g1_[1], g1_[2], g1_[3]); \
        *(uint4*)((stc_) + 3 * TILE_BYTES + sts_b + 16) = make_uint4(g1_[4], g1_[5], g1_[6], g1_[7]); \
    } while (0)

    // ---- preload chunk 0 --------------------------------------------------
    {
        float4 sa[4];
        uint4  pb[4];
#pragma unroll
        for (int q = 0; q < 4; q++) {
            sa[q] = *(const float4*)(Ag + 4 * q);
            pb[q] = *(const uint4*)(Bg + 4 * q);
        }
        STASH_A(smh, sa);
        STASH_B(smc, pb);
    }
    __syncthreads();

    // ---- main loop (R13 structure) ----------------------------------------
    for (int c = 0; c < NCH; c++) {
        const int s = c & 1;
        const bool hasNext = (c + 1 < NCH);

        float4 sa[4];
        uint4  pb[4];
        if (hasNext) {
            const float*    ap = Ag + (size_t)(c + 1) * BK;
            const uint32_t* bp = Bg + (size_t)(c + 1) * BK;
#pragma unroll
            for (int q = 0; q < 4; q++) {
                sa[q] = *(const float4*)(ap + 4 * q);
                pb[q] = *(const uint4*)(bp + 4 * q);
            }
        }

        const uint32_t so = (uint32_t)s * STAGE_BYTES;
#pragma unroll
        for (int ks = 0; ks < 2; ks++) {
            const uint32_t ko = so + ks * 32u;

            uint32_t a0[2][4], a1[2][4];
#pragma unroll
            for (int i = 0; i < 2; i++) {
                LDMX4(a0[i][0], a0[i][1], a0[i][2], a0[i][3], aAdr[i] + ko);
                LDMX4(a1[i][0], a1[i][1], a1[i][2], a1[i][3],
                      aAdr[i] + ko + TILE_BYTES);
            }
            uint32_t b0[8][2], b1[8][2];
#pragma unroll
            for (int jp = 0; jp < 4; jp++) {
                LDMX4(b0[2 * jp][0], b0[2 * jp][1], b0[2 * jp + 1][0],
                      b0[2 * jp + 1][1], bAdr[jp] + ko);
                LDMX4(b1[2 * jp][0], b1[2 * jp][1], b1[2 * jp + 1][0],
                      b1[2 * jp + 1][1], bAdr[jp] + ko + TILE_BYTES);
            }
#pragma unroll
            for (int i = 0; i < 2; i++)
#pragma unroll
                for (int j = 0; j < 8; j++) {
                    mma_f32(acc[i][j], a0[i], b0[j]);
                    mma_f16(xacc[i][j], a0[i], b1[j]);
                    mma_f16(xacc[i][j], a1[i], b0[j]);
                }
        }

        if (hasNext) {
            __half* st  = smh + (s ^ 1) * STAGE_H;
            char*   stc = smc + (s ^ 1) * STAGE_BYTES;
            STASH_A(st, sa);
            STASH_B(stc, pb);
        }
        __syncthreads();
    }
#undef STASH_A
#undef STASH_B

    // ---- epilogue: main + cross term --------------------------------------
    float* Cb  = C + (size_t)blockIdx.z * cB + (size_t)blockIdx.x * BN;
    float* C2b = C2 ? C2 + (size_t)blockIdx.z * c2B + (size_t)blockIdx.x * BN
                    : nullptr;
#pragma unroll
    for (int i = 0; i < 2; i++) {
        const size_t mTop = (size_t)blockIdx.y * BM + wm * 32 + i * 16 + lr;
#pragma unroll
        for (int j = 0; j < 8; j++) {
            const int n0 = wn * 64 + j * 8 + 2 * lc;
            float2 x0 = __half22float2(*(__half2*)&xacc[i][j][0]);
            float2 x1 = __half22float2(*(__half2*)&xacc[i][j][1]);
            float2 v0 = make_float2(acc[i][j][0] + x0.x, acc[i][j][1] + x0.y);
            float2 v1 = make_float2(acc[i][j][2] + x1.x, acc[i][j][3] + x1.y);
            *(float2*)(Cb + mTop * ldc + n0)       = v0;
            *(float2*)(Cb + (mTop + 8) * ldc + n0) = v1;
            if (C2b) {
                *(float2*)(C2b + mTop * ldc2 + n0)       = v0;
                *(float2*)(C2b + (mTop + 8) * ldc2 + n0) = v1;
            }
        }
    }
}

// ---------------------------------------------------------------------------
// Elementwise fp32 -> packed uint32, same indexing.
// ---------------------------------------------------------------------------
__global__ __launch_bounds__(256)
void pack_f32(const float* __restrict__ in, uint2* __restrict__ out, int n2)
{
    int i = blockIdx.x * 256 + threadIdx.x;
    if (i < n2) {
        float2 v = ((const float2*)in)[i];
        out[i] = pack2(v.x, v.y);
    }
}

// ---------------------------------------------------------------------------
// sent (b,512,1024) fp32 -> packed sent^T (b,1024,512)
// ---------------------------------------------------------------------------
__global__ __launch_bounds__(256)
void transpose_pack(const float* __restrict__ sent, uint32_t* __restrict__ outp)
{
    __shared__ float t[32][33];
    const int b  = blockIdx.z;
    const int n0 = blockIdx.y * 32;
    const int e0 = blockIdx.x * 32;
    const int x = threadIdx.x, y = threadIdx.y;

    const float* src = sent + ((size_t)b * NS_ + n0) * E_ + e0;
#pragma unroll
    for (int k = 0; k < 4; k++)
        t[y + 8 * k][x] = src[(size_t)(y + 8 * k) * E_ + x];
    __syncthreads();
    const size_t dbase = ((size_t)b * E_ + e0) * NS_ + n0;
#pragma unroll
    for (int k = 0; k < 4; k++) {
        float v = t[x][y + 8 * k];
        __half h0 = __float2half_rn(v);
        __half h1 = __float2half_rn(v - __half2float(h0));
        outp[dbase + (size_t)(y + 8 * k) * NS_ + x] =
            ((uint32_t)__half_as_ushort(h1) << 16) | __half_as_ushort(h0);
    }
}

// ---------------------------------------------------------------------------
// In-place stable softmax over last dim (512) of g_scores.
// ---------------------------------------------------------------------------
__global__ __launch_bounds__(256)
void softmax_rows()
{
    __shared__ float redMax[8];
    __shared__ float redSum[8];

    float* row = g_scores + (size_t)blockIdx.x * NS_;
    const int t = threadIdx.x;

    float2 v = reinterpret_cast<float2*>(row)[t];

    float m = fmaxf(v.x, v.y);
#pragma unroll
    for (int o = 16; o > 0; o >>= 1)
        m = fmaxf(m, __shfl_xor_sync(0xffffffffu, m, o));
    if ((t & 31) == 0) redMax[t >> 5] = m;
    __syncthreads();
    float mAll = redMax[0];
#pragma unroll
    for (int i = 1; i < 8; i++) mAll = fmaxf(mAll, redMax[i]);

    float e0 = expf(v.x - mAll);
    float e1 = expf(v.y - mAll);
    float s = e0 + e1;
#pragma unroll
    for (int o = 16; o > 0; o >>= 1)
        s += __shfl_xor_sync(0xffffffffu, s, o);
    if ((t & 31) == 0) redSum[t >> 5] = s;
    __syncthreads();
    float sAll = 0.f;
#pragma unroll
    for (int i = 0; i < 8; i++) sAll += redSum[i];

    const float inv = 1.0f / sAll;
    reinterpret_cast<float2*>(row)[t] = make_float2(e0 * inv, e1 * inv);
}

// ---------------------------------------------------------------------------
extern "C" void kernel_launch(void* const* d_in, const int* in_sizes, int n_in,
                              void* d_out, int out_size)
{
    (void)out_size;
    const float* word = nullptr;
    const float* sent = nullptr;
    const float* W    = nullptr;
    for (int i = 0; i < n_in; i++) {
        if      (in_sizes[i] == M_TOT * E_)    word = (const float*)d_in[i];
        else if (in_sizes[i] == B_ * NS_ * E_) sent = (const float*)d_in[i];
        else if (in_sizes[i] == E_ * E_)       W    = (const float*)d_in[i];
    }

    float* out  = (float*)d_out;
    float* comb = out;                               // (8, 2048, 2048)
    float* gout = out + (size_t)M_TOT * 2 * E_;      // (8, 2048, 1024)

    float    *scores;
    uint32_t *Wp, *sentp, *sentTp;
    cudaGetSymbolAddress((void**)&scores, g_scores);
    cudaGetSymbolAddress((void**)&Wp,     g_Wp);
    cudaGetSymbolAddress((void**)&sentp,  g_sentp);
    cudaGetSymbolAddress((void**)&sentTp, g_sentTp);

    cudaFuncSetAttribute(gemm3hb,
                         cudaFuncAttributeMaxDynamicSharedMemorySize, DYN_SMEM);

    // 0) pack B-side operands (bandwidth-bound)
    pack_f32<<<(E_ * E_ / 2 + 255) / 256, 256>>>(W, (uint2*)Wp, E_ * E_ / 2);
    pack_f32<<<(B_ * NS_ * E_ / 2 + 255) / 256, 256>>>(sent, (uint2*)sentp,
                                                       B_ * NS_ * E_ / 2);
    transpose_pack<<<dim3(E_ / 32, NS_ / 32, B_), dim3(32, 8)>>>(sent, sentTp);

    // 1) w = word @ W^T -> combination[:, :1024]   (M=16384, N=1024, K=1024)
    gemm3hb<<<dim3(E_ / BN, M_TOT / BM, 1), NTHREADS, DYN_SMEM>>>(
        word, Wp, comb, nullptr,
        E_, E_, 2 * E_, 0, E_,
        0, 0, 0, 0);

    // 2) scores[b] = w[b] @ sent[b]^T -> g_scores  (M=2048, N=512, K=1024)
    gemm3hb<<<dim3(NS_ / BN, S_ / BM, B_), NTHREADS, DYN_SMEM>>>(
        comb, sentp, scores, nullptr,
        2 * E_, E_, NS_, 0, E_,
        (size_t)S_ * 2 * E_, (size_t)NS_ * E_, (size_t)S_ * NS_, 0);

    // 3) softmax over 512 sentence scores per (b,s) row
    softmax_rows<<<M_TOT, 256>>>();

    // 4) g[b] = att[b] @ sent[b] -> comb[:, 1024:] AND g  (M=2048, N=1024, K=512)
    gemm3hb<<<dim3(E_ / BN, S_ / BM, B_), NTHREADS, DYN_SMEM>>>(
        scores, sentTp, comb + E_, gout,
        NS_, NS_, 2 * E_, E_, NS_,
        (size_t)S_ * NS_, (size_t)E_ * NS_, (size_t)S_ * 2 * E_, (size_t)S_ * E_);
}